// round 6
// baseline (speedup 1.0000x reference)
#include <cuda_runtime.h>
#include <cuda_fp16.h>
#include <cstdint>

// ---------------- problem constants ----------------
#define BB    64
#define HH    64
#define WWID  64
#define CINC  128
#define COUTC 256
#define HOUT  62
#define WOUT  62
#define MM    3844
#define KKTOT 1152
#define NNTOT 256

// ---------------- GEMM tiling ----------------
#define BM     128
#define BN     256
#define BK     64
#define NIT    (KKTOT / BK)   // 18
#define STAGES 4
#define NTHREADS 256

// smem (halves): As[s][128][72], Bs[s][64][264]
#define A_ROW_H 72
#define B_ROW_H 264
#define A_ST_H  (BM * A_ROW_H)   // 9216  halves = 18432 B
#define B_ST_H  (BK * B_ROW_H)   // 16896 halves = 33792 B
#define SMEM_A  0
#define SMEM_B  (STAGES * A_ST_H * 2)                 // 73728
#define SMEM_TOTAL (SMEM_B + STAGES * B_ST_H * 2)     // 73728 + 135168 = 208896

// ---------------- scratch ----------------
__device__ __half g_Xh[(size_t)BB * HH * WWID * CINC];   // X fp16 NHWC
__device__ __half g_Wh[(size_t)BB * KKTOT * COUTC];      // memW fp16 [b][k][n]

// ---------------- fused prep ----------------
#define XBLOCKS 32768
#define WBLOCKS 18432
__global__ void prep_kernel(const float* __restrict__ X,
                            const float* __restrict__ W,
                            const float* __restrict__ Werr) {
    if (blockIdx.x < XBLOCKS) {
        size_t i = ((size_t)blockIdx.x * blockDim.x + threadIdx.x) * 4;
        float4 v = *reinterpret_cast<const float4*>(X + i);
        __half2 h0 = __floats2half2_rn(v.x, v.y);
        __half2 h1 = __floats2half2_rn(v.z, v.w);
        uint2 o;
        o.x = *reinterpret_cast<uint32_t*>(&h0);
        o.y = *reinterpret_cast<uint32_t*>(&h1);
        *reinterpret_cast<uint2*>(g_Xh + i) = o;
    } else {
        size_t i = ((size_t)(blockIdx.x - XBLOCKS) * blockDim.x + threadIdx.x) * 4;
        size_t wi = i % ((size_t)KKTOT * COUTC);
        float4 w = *reinterpret_cast<const float4*>(W + wi);
        float4 e = *reinterpret_cast<const float4*>(Werr + i);
        __half2 h0 = __floats2half2_rn(w.x * e.x, w.y * e.y);
        __half2 h1 = __floats2half2_rn(w.z * e.z, w.w * e.w);
        uint2 o;
        o.x = *reinterpret_cast<uint32_t*>(&h0);
        o.y = *reinterpret_cast<uint32_t*>(&h1);
        *reinterpret_cast<uint2*>(g_Wh + i) = o;
    }
}

// ---------------- PTX helpers ----------------
__device__ __forceinline__ void cp16(uint32_t dst, const void* src) {
    asm volatile("cp.async.cg.shared.global [%0], [%1], 16;\n" :: "r"(dst), "l"(src));
}
__device__ __forceinline__ void cp_commit() {
    asm volatile("cp.async.commit_group;\n" ::: "memory");
}
template <int N>
__device__ __forceinline__ void cp_wait() {
    asm volatile("cp.async.wait_group %0;\n" :: "n"(N) : "memory");
}
__device__ __forceinline__ void ldmatrix_x4(uint32_t* r, uint32_t addr) {
    asm volatile("ldmatrix.sync.aligned.m8n8.x4.shared.b16 {%0,%1,%2,%3}, [%4];\n"
                 : "=r"(r[0]), "=r"(r[1]), "=r"(r[2]), "=r"(r[3]) : "r"(addr));
}
__device__ __forceinline__ void ldmatrix_x4_trans(uint32_t* r, uint32_t addr) {
    asm volatile("ldmatrix.sync.aligned.m8n8.x4.trans.shared.b16 {%0,%1,%2,%3}, [%4];\n"
                 : "=r"(r[0]), "=r"(r[1]), "=r"(r[2]), "=r"(r[3]) : "r"(addr));
}
__device__ __forceinline__ void mma16816(float* c, const uint32_t* a, const uint32_t* b) {
    asm volatile(
        "mma.sync.aligned.m16n8k16.row.col.f32.f16.f16.f32 "
        "{%0,%1,%2,%3}, {%4,%5,%6,%7}, {%8,%9}, {%0,%1,%2,%3};\n"
        : "+f"(c[0]), "+f"(c[1]), "+f"(c[2]), "+f"(c[3])
        : "r"(a[0]), "r"(a[1]), "r"(a[2]), "r"(a[3]), "r"(b[0]), "r"(b[1]));
}

// ---------------- main GEMM ----------------
// grid (31, 64), 256 threads, 8 warps as 2(M) x 4(N); warp tile 64x64.
__global__ __launch_bounds__(NTHREADS, 1)
void conv_gemm_kernel(const float* __restrict__ bias,
                      const float* __restrict__ Berr,
                      float* __restrict__ out) {
    extern __shared__ __align__(16) char smem[];
    const uint32_t sbase = (uint32_t)__cvta_generic_to_shared(smem);

    const int tid  = threadIdx.x;
    const int warp = tid >> 5;
    const int lane = tid & 31;
    const int wm = warp >> 2;   // 0..1
    const int wn = warp & 3;    // 0..3
    const int m0 = blockIdx.x * BM;
    const int b  = blockIdx.y;

    float acc[4][8][4];
    #pragma unroll
    for (int mf = 0; mf < 4; mf++)
        #pragma unroll
        for (int nf = 0; nf < 8; nf++)
            #pragma unroll
            for (int r = 0; r < 4; r++) acc[mf][nf][r] = 0.f;

    // A: 128 rows x 8 chunks = 1024 chunks/stage -> 4/thread
    const int arow0 = tid >> 3;
    const int aseg  = tid & 7;
    size_t abase[4];
    #pragma unroll
    for (int j = 0; j < 4; j++) {
        int m = m0 + arow0 + j * 32;
        if (m >= MM) m = 0;
        int ho = m / WOUT;
        int wo = m - ho * WOUT;
        abase[j] = (((size_t)b * HH + ho) * WWID + wo) * CINC;
    }
    const size_t wbase = (size_t)b * KKTOT * COUTC;

    auto issue_stage = [&](int it, int slot) {
        const int k0 = it * BK;
        const int tap = k0 >> 7;
        const int c0  = k0 & 127;
        const int kh  = tap / 3;
        const int kw  = tap - kh * 3;
        const size_t tapoff = ((size_t)kh * WWID + kw) * CINC + c0;
        const uint32_t a0 = sbase + SMEM_A + slot * A_ST_H * 2;
        const uint32_t b0 = sbase + SMEM_B + slot * B_ST_H * 2;
        #pragma unroll
        for (int j = 0; j < 4; j++) {
            const __half* src = g_Xh + abase[j] + tapoff + aseg * 8;
            cp16(a0 + ((arow0 + j * 32) * A_ROW_H + aseg * 8) * 2, src);
        }
        #pragma unroll
        for (int j = 0; j < 8; j++) {      // B: 64 rows x 32 chunks = 2048
            int c = tid + j * 256;
            int row = c >> 5;
            int seg = c & 31;
            const __half* src = g_Wh + wbase + (size_t)(k0 + row) * COUTC + seg * 8;
            cp16(b0 + (row * B_ROW_H + seg * 8) * 2, src);
        }
    };

    // prologue: 3 stages in flight
    issue_stage(0, 0); cp_commit();
    issue_stage(1, 1); cp_commit();
    issue_stage(2, 2); cp_commit();

    for (int it = 0; it < NIT; it++) {
        const int s = it & (STAGES - 1);
        if (it <= NIT - 3)      cp_wait<2>();
        else if (it == NIT - 2) cp_wait<1>();
        else                    cp_wait<0>();
        __syncthreads();
        if (it + 3 < NIT) { issue_stage(it + 3, (it + 3) & (STAGES - 1)); cp_commit(); }

        const uint32_t aS = sbase + SMEM_A + s * A_ST_H * 2;
        const uint32_t bS = sbase + SMEM_B + s * B_ST_H * 2;
        #pragma unroll
        for (int ks = 0; ks < 4; ks++) {
            uint32_t afr[4][4];
            const int arL  = wm * 64 + (lane & 15);
            const int acol = ks * 16 + ((lane >> 4) << 3);
            #pragma unroll
            for (int mf = 0; mf < 4; mf++)
                ldmatrix_x4(afr[mf], aS + ((arL + mf * 16) * A_ROW_H + acol) * 2);

            // B: x4.trans fetches two n8 fragments (16 cols) per LDSM
            uint32_t bfr[8][2];
            {
                const int brow = ks * 16 + ((lane >> 3) & 1) * 8 + (lane & 7);
                #pragma unroll
                for (int p = 0; p < 4; p++) {
                    const int bcol = wn * 64 + p * 16 + (lane >> 4) * 8;
                    uint32_t r[4];
                    ldmatrix_x4_trans(r, bS + (brow * B_ROW_H + bcol) * 2);
                    bfr[2 * p][0]     = r[0];
                    bfr[2 * p][1]     = r[1];
                    bfr[2 * p + 1][0] = r[2];
                    bfr[2 * p + 1][1] = r[3];
                }
            }

            #pragma unroll
            for (int mf = 0; mf < 4; mf++)
                #pragma unroll
                for (int nf = 0; nf < 8; nf++)
                    mma16816(acc[mf][nf], afr[mf], bfr[nf]);
        }
    }

    // epilogue: fused noisy bias, f32 stores
    const int gid = lane >> 2;
    const int tg  = lane & 3;
    #pragma unroll
    for (int nf = 0; nf < 8; nf++) {
        const int cc = wn * 64 + nf * 8 + tg * 2;
        const float mb0 = bias[cc]     * Berr[b * COUTC + cc];
        const float mb1 = bias[cc + 1] * Berr[b * COUTC + cc + 1];
        #pragma unroll
        for (int mf = 0; mf < 4; mf++) {
            const int r0 = m0 + wm * 64 + mf * 16 + gid;
            if (r0 < MM) {
                float2 v = make_float2(acc[mf][nf][0] + mb0, acc[mf][nf][1] + mb1);
                *reinterpret_cast<float2*>(&out[((size_t)b * MM + r0) * NNTOT + cc]) = v;
            }
            const int r1 = r0 + 8;
            if (r1 < MM) {
                float2 v = make_float2(acc[mf][nf][2] + mb0, acc[mf][nf][3] + mb1);
                *reinterpret_cast<float2*>(&out[((size_t)b * MM + r1) * NNTOT + cc]) = v;
            }
        }
    }
}

// ---------------- launch ----------------
extern "C" void kernel_launch(void* const* d_in, const int* in_sizes, int n_in,
                              void* d_out, int out_size) {
    (void)in_sizes; (void)n_in; (void)out_size;
    const float* X    = (const float*)d_in[0];
    const float* W    = (const float*)d_in[1];
    const float* bias = (const float*)d_in[2];
    const float* Werr = (const float*)d_in[3];
    const float* Berr = (const float*)d_in[4];
    float* out = (float*)d_out;

    prep_kernel<<<XBLOCKS + WBLOCKS, 256>>>(X, W, Werr);

    static bool attr_set = false;
    if (!attr_set) {
        cudaFuncSetAttribute(conv_gemm_kernel,
                             cudaFuncAttributeMaxDynamicSharedMemorySize, SMEM_TOTAL);
        attr_set = true;
    }
    dim3 grid((MM + BM - 1) / BM, BB);   // (31, 64)
    conv_gemm_kernel<<<grid, NTHREADS, SMEM_TOTAL>>>(bias, Berr, out);
}

// round 7
// speedup vs baseline: 1.1396x; 1.1396x over previous
#include <cuda_runtime.h>
#include <cuda_fp16.h>
#include <cstdint>

// ---------------- problem constants ----------------
#define BB    64
#define HH    64
#define WWID  64
#define CINC  128
#define COUTC 256
#define HOUT  62
#define WOUT  62
#define MM    3844
#define KKTOT 1152
#define NNTOT 256

// ---------------- GEMM tiling ----------------
#define BM     128
#define BN     128
#define BK     64
#define NIT    (KKTOT / BK)   // 18
#define STAGES 3
#define NTHREADS 256

// smem (halves): As[s][128][72], Bs[s][64][136]
#define A_ROW_H 72
#define B_ROW_H 136
#define A_ST_H  (BM * A_ROW_H)   // 9216 halves  = 18432 B
#define B_ST_H  (BK * B_ROW_H)   // 8704 halves  = 17408 B
#define SMEM_A  0
#define SMEM_B  (STAGES * A_ST_H * 2)                  // 55296
#define SMEM_TOTAL (SMEM_B + STAGES * B_ST_H * 2)      // 55296 + 52224 = 107520

// ---------------- scratch ----------------
__device__ __half g_Xh[(size_t)BB * HH * WWID * CINC];   // X fp16 NHWC
__device__ __half g_Wh[(size_t)BB * KKTOT * COUTC];      // memW fp16 [b][k][n]

// ---------------- fused prep ----------------
#define XBLOCKS 32768
#define WBLOCKS 18432
__global__ void prep_kernel(const float* __restrict__ X,
                            const float* __restrict__ W,
                            const float* __restrict__ Werr) {
    if (blockIdx.x < XBLOCKS) {
        size_t i = ((size_t)blockIdx.x * blockDim.x + threadIdx.x) * 4;
        float4 v = *reinterpret_cast<const float4*>(X + i);
        __half2 h0 = __floats2half2_rn(v.x, v.y);
        __half2 h1 = __floats2half2_rn(v.z, v.w);
        uint2 o;
        o.x = *reinterpret_cast<uint32_t*>(&h0);
        o.y = *reinterpret_cast<uint32_t*>(&h1);
        *reinterpret_cast<uint2*>(g_Xh + i) = o;
    } else {
        size_t i = ((size_t)(blockIdx.x - XBLOCKS) * blockDim.x + threadIdx.x) * 4;
        size_t wi = i % ((size_t)KKTOT * COUTC);
        float4 w = *reinterpret_cast<const float4*>(W + wi);
        float4 e = *reinterpret_cast<const float4*>(Werr + i);
        __half2 h0 = __floats2half2_rn(w.x * e.x, w.y * e.y);
        __half2 h1 = __floats2half2_rn(w.z * e.z, w.w * e.w);
        uint2 o;
        o.x = *reinterpret_cast<uint32_t*>(&h0);
        o.y = *reinterpret_cast<uint32_t*>(&h1);
        *reinterpret_cast<uint2*>(g_Wh + i) = o;
    }
}

// ---------------- PTX helpers ----------------
__device__ __forceinline__ void cp16(uint32_t dst, const void* src) {
    asm volatile("cp.async.cg.shared.global [%0], [%1], 16;\n" :: "r"(dst), "l"(src));
}
__device__ __forceinline__ void cp_commit() {
    asm volatile("cp.async.commit_group;\n" ::: "memory");
}
template <int N>
__device__ __forceinline__ void cp_wait() {
    asm volatile("cp.async.wait_group %0;\n" :: "n"(N) : "memory");
}
__device__ __forceinline__ void ldmatrix_x4(uint32_t* r, uint32_t addr) {
    asm volatile("ldmatrix.sync.aligned.m8n8.x4.shared.b16 {%0,%1,%2,%3}, [%4];\n"
                 : "=r"(r[0]), "=r"(r[1]), "=r"(r[2]), "=r"(r[3]) : "r"(addr));
}
__device__ __forceinline__ void ldmatrix_x4_trans(uint32_t* r, uint32_t addr) {
    asm volatile("ldmatrix.sync.aligned.m8n8.x4.trans.shared.b16 {%0,%1,%2,%3}, [%4];\n"
                 : "=r"(r[0]), "=r"(r[1]), "=r"(r[2]), "=r"(r[3]) : "r"(addr));
}
__device__ __forceinline__ void mma16816(float* c, const uint32_t* a, const uint32_t* b) {
    asm volatile(
        "mma.sync.aligned.m16n8k16.row.col.f32.f16.f16.f32 "
        "{%0,%1,%2,%3}, {%4,%5,%6,%7}, {%8,%9}, {%0,%1,%2,%3};\n"
        : "+f"(c[0]), "+f"(c[1]), "+f"(c[2]), "+f"(c[3])
        : "r"(a[0]), "r"(a[1]), "r"(a[2]), "r"(a[3]), "r"(b[0]), "r"(b[1]));
}

// ---------------- main GEMM ----------------
// grid (2, 31, 64), 256 threads (2x4 warps, warp tile 64x32)
// 3-stage cp.async ring, wait<1>, single barrier per iteration.
__global__ __launch_bounds__(NTHREADS, 2)
void conv_gemm_kernel(const float* __restrict__ bias,
                      const float* __restrict__ Berr,
                      float* __restrict__ out) {
    extern __shared__ __align__(16) char smem[];
    const uint32_t sbase = (uint32_t)__cvta_generic_to_shared(smem);

    const int tid  = threadIdx.x;
    const int warp = tid >> 5;
    const int lane = tid & 31;
    const int wm = warp >> 2;
    const int wn = warp & 3;
    const int n0 = blockIdx.x * BN;
    const int m0 = blockIdx.y * BM;
    const int b  = blockIdx.z;

    float acc[4][4][4];
    #pragma unroll
    for (int mf = 0; mf < 4; mf++)
        #pragma unroll
        for (int nf = 0; nf < 4; nf++)
            #pragma unroll
            for (int r = 0; r < 4; r++) acc[mf][nf][r] = 0.f;

    // A: 128 rows x 8 chunks = 1024 chunks/stage -> 4/thread
    const int arow0 = tid >> 3;
    const int aseg  = tid & 7;
    size_t abase[4];
    #pragma unroll
    for (int j = 0; j < 4; j++) {
        int m = m0 + arow0 + j * 32;
        if (m >= MM) m = 0;
        int ho = m / WOUT;
        int wo = m - ho * WOUT;
        abase[j] = (((size_t)b * HH + ho) * WWID + wo) * CINC;
    }
    const size_t wbase = (size_t)b * KKTOT * COUTC;

    auto issue_stage = [&](int it, int slot) {
        const int k0 = it * BK;
        const int tap = k0 >> 7;
        const int c0  = k0 & 127;
        const int kh  = tap / 3;
        const int kw  = tap - kh * 3;
        const size_t tapoff = ((size_t)kh * WWID + kw) * CINC + c0;
        const uint32_t a0 = sbase + SMEM_A + slot * A_ST_H * 2;
        const uint32_t b0 = sbase + SMEM_B + slot * B_ST_H * 2;
        #pragma unroll
        for (int j = 0; j < 4; j++) {
            const __half* src = g_Xh + abase[j] + tapoff + aseg * 8;
            cp16(a0 + ((arow0 + j * 32) * A_ROW_H + aseg * 8) * 2, src);
        }
        #pragma unroll
        for (int j = 0; j < 4; j++) {          // B: 64 rows x 16 chunks
            int c = tid + j * 256;
            int row = c >> 4;
            int seg = c & 15;
            const __half* src = g_Wh + wbase + (size_t)(k0 + row) * COUTC + n0 + seg * 8;
            cp16(b0 + (row * B_ROW_H + seg * 8) * 2, src);
        }
    };

    // prologue: 2 stages in flight
    issue_stage(0, 0); cp_commit();
    issue_stage(1, 1); cp_commit();

    for (int it = 0; it < NIT; it++) {
        const int s = it % STAGES;
        if (it == NIT - 1) cp_wait<0>(); else cp_wait<1>();
        __syncthreads();
        if (it + 2 < NIT) { issue_stage(it + 2, (it + 2) % STAGES); cp_commit(); }

        const uint32_t aS = sbase + SMEM_A + s * A_ST_H * 2;
        const uint32_t bS = sbase + SMEM_B + s * B_ST_H * 2;
        #pragma unroll
        for (int ks = 0; ks < 4; ks++) {
            // B first: 2x ldmatrix.x4.trans -> 4 n8 fragments
            uint32_t bfr[4][2];
            {
                const int brow = ks * 16 + ((lane >> 3) & 1) * 8 + (lane & 7);
                #pragma unroll
                for (int p = 0; p < 2; p++) {
                    const int bcol = wn * 32 + p * 16 + (lane >> 4) * 8;
                    uint32_t r[4];
                    ldmatrix_x4_trans(r, bS + (brow * B_ROW_H + bcol) * 2);
                    bfr[2 * p][0]     = r[0];
                    bfr[2 * p][1]     = r[1];
                    bfr[2 * p + 1][0] = r[2];
                    bfr[2 * p + 1][1] = r[3];
                }
            }
            uint32_t afr[4][4];
            const int arL  = wm * 64 + (lane & 15);
            const int acol = ks * 16 + ((lane >> 4) << 3);
            #pragma unroll
            for (int mf = 0; mf < 4; mf++)
                ldmatrix_x4(afr[mf], aS + ((arL + mf * 16) * A_ROW_H + acol) * 2);

            #pragma unroll
            for (int mf = 0; mf < 4; mf++)
                #pragma unroll
                for (int nf = 0; nf < 4; nf++)
                    mma16816(acc[mf][nf], afr[mf], bfr[nf]);
        }
    }

    // epilogue: fused noisy bias, f32 stores
    const int gid = lane >> 2;
    const int tg  = lane & 3;
    #pragma unroll
    for (int nf = 0; nf < 4; nf++) {
        const int cc = n0 + wn * 32 + nf * 8 + tg * 2;
        const float mb0 = bias[cc]     * Berr[b * COUTC + cc];
        const float mb1 = bias[cc + 1] * Berr[b * COUTC + cc + 1];
        #pragma unroll
        for (int mf = 0; mf < 4; mf++) {
            const int r0 = m0 + wm * 64 + mf * 16 + gid;
            if (r0 < MM) {
                float2 v = make_float2(acc[mf][nf][0] + mb0, acc[mf][nf][1] + mb1);
                *reinterpret_cast<float2*>(&out[((size_t)b * MM + r0) * NNTOT + cc]) = v;
            }
            const int r1 = r0 + 8;
            if (r1 < MM) {
                float2 v = make_float2(acc[mf][nf][2] + mb0, acc[mf][nf][3] + mb1);
                *reinterpret_cast<float2*>(&out[((size_t)b * MM + r1) * NNTOT + cc]) = v;
            }
        }
    }
}

// ---------------- launch ----------------
extern "C" void kernel_launch(void* const* d_in, const int* in_sizes, int n_in,
                              void* d_out, int out_size) {
    (void)in_sizes; (void)n_in; (void)out_size;
    const float* X    = (const float*)d_in[0];
    const float* W    = (const float*)d_in[1];
    const float* bias = (const float*)d_in[2];
    const float* Werr = (const float*)d_in[3];
    const float* Berr = (const float*)d_in[4];
    float* out = (float*)d_out;

    prep_kernel<<<XBLOCKS + WBLOCKS, 256>>>(X, W, Werr);

    static bool attr_set = false;
    if (!attr_set) {
        cudaFuncSetAttribute(conv_gemm_kernel,
                             cudaFuncAttributeMaxDynamicSharedMemorySize, SMEM_TOTAL);
        attr_set = true;
    }
    dim3 grid(NNTOT / BN, (MM + BM - 1) / BM, BB);   // (2, 31, 64)
    conv_gemm_kernel<<<grid, NTHREADS, SMEM_TOTAL>>>(bias, Berr, out);
}